// round 6
// baseline (speedup 1.0000x reference)
#include <cuda_runtime.h>
#include <math.h>
#include <string.h>

#define BS 8
#define LQ 300
#define NQ (BS*LQ)        // 2400
#define DIM 256
#define NH 8
#define NL 4
#define NP 4
#define LEN_V 34000
#define NPOINT 128        // NH*NL*NP

__constant__ int c_lvlW[4]     = {160, 80, 40, 20};
__constant__ int c_lvlStart[4] = {0, 25600, 32000, 33600};

// Scratch
__device__ float g_P[NQ * 384];                    // [off(256) | attn(128)]
__device__ float g_agg[(size_t)NH * NQ * DIM];     // [h][q][c]
__device__ float g_wsum[NQ * NH];
__device__ float g_Y[NQ * DIM];

// Packed fp32x2 FMA (Blackwell): d = a*b + d per 32-bit lane of the 64-bit pair.
#define FFMA2(c, a, b) asm("fma.rn.f32x2 %0, %1, %2, %0;" : "+l"(c) : "l"(a), "l"(b))

__device__ __forceinline__ float2 unpack2(unsigned long long v) {
    float2 f; memcpy(&f, &v, 8); return f;
}

// ---------------------------------------------------------------------------
// FFMA2 GEMM, dual weight set. Tile 64(M) x 64(N), 128 threads.
// Micro-tile 8(M, as 4 packed f32x2 row-pairs) x 4(N).
// B kept DUPLICATED in smem so packed b operands come straight from LDS.128.
// ---------------------------------------------------------------------------
__global__ void __launch_bounds__(128) gemm_dual_kernel(
    const float* __restrict__ A, int lda,
    const float* __restrict__ W0, const float* __restrict__ b0, int nyW0,
    const float* __restrict__ W1, const float* __restrict__ b1,
    float* __restrict__ C, int ldc, int M)
{
    __shared__ __align__(16) float As[2][16][68];    // [buf][k][row]
    __shared__ __align__(16) float Bs[2][16][128];   // [buf][k][2j]=[2j+1]=b_j
    const int tid = threadIdx.x;
    const int tx = tid & 7;           // rows tx*8 .. tx*8+7
    const int ty = tid >> 3;          // cols ty*4 .. ty*4+3
    const int row0 = blockIdx.x * 64;
    const int lr = tid >> 1;          // 0..63 (loader row / col)
    const int lk = (tid & 1) * 8;     // k offset 0 or 8

    const float* W; const float* bias; int col0, colOff;
    if ((int)blockIdx.y < nyW0) {
        W = W0; bias = b0; col0 = blockIdx.y * 64; colOff = 0;
    } else {
        W = W1; bias = b1; col0 = (blockIdx.y - nyW0) * 64; colOff = nyW0 * 64;
    }

    int arow = row0 + lr; if (arow >= M) arow = M - 1;
    const float* aptr = A + (size_t)arow * lda + lk;
    const float* wptr = W + (size_t)(col0 + lr) * 256 + lk;

    unsigned long long acc[4][4];
#pragma unroll
    for (int i = 0; i < 4; ++i)
#pragma unroll
        for (int j = 0; j < 4; ++j) acc[i][j] = 0ull;

    float4 va0 = *(const float4*)(aptr);
    float4 va1 = *(const float4*)(aptr + 4);
    float4 vw0 = *(const float4*)(wptr);
    float4 vw1 = *(const float4*)(wptr + 4);

    int buf = 0;
    for (int kc = 0; kc < 256; kc += 16) {
        As[buf][lk + 0][lr] = va0.x; As[buf][lk + 1][lr] = va0.y;
        As[buf][lk + 2][lr] = va0.z; As[buf][lk + 3][lr] = va0.w;
        As[buf][lk + 4][lr] = va1.x; As[buf][lk + 5][lr] = va1.y;
        As[buf][lk + 6][lr] = va1.z; As[buf][lk + 7][lr] = va1.w;
        *(float2*)&Bs[buf][lk + 0][2 * lr] = make_float2(vw0.x, vw0.x);
        *(float2*)&Bs[buf][lk + 1][2 * lr] = make_float2(vw0.y, vw0.y);
        *(float2*)&Bs[buf][lk + 2][2 * lr] = make_float2(vw0.z, vw0.z);
        *(float2*)&Bs[buf][lk + 3][2 * lr] = make_float2(vw0.w, vw0.w);
        *(float2*)&Bs[buf][lk + 4][2 * lr] = make_float2(vw1.x, vw1.x);
        *(float2*)&Bs[buf][lk + 5][2 * lr] = make_float2(vw1.y, vw1.y);
        *(float2*)&Bs[buf][lk + 6][2 * lr] = make_float2(vw1.z, vw1.z);
        *(float2*)&Bs[buf][lk + 7][2 * lr] = make_float2(vw1.w, vw1.w);
        __syncthreads();
        if (kc + 16 < 256) {
            va0 = *(const float4*)(aptr + kc + 16);
            va1 = *(const float4*)(aptr + kc + 20);
            vw0 = *(const float4*)(wptr + kc + 16);
            vw1 = *(const float4*)(wptr + kc + 20);
        }
#pragma unroll
        for (int k = 0; k < 16; ++k) {
            ulonglong2 a01 = *(const ulonglong2*)&As[buf][k][tx * 8];
            ulonglong2 a23 = *(const ulonglong2*)&As[buf][k][tx * 8 + 4];
            ulonglong2 b01 = *(const ulonglong2*)&Bs[buf][k][ty * 8];
            ulonglong2 b23 = *(const ulonglong2*)&Bs[buf][k][ty * 8 + 4];
            FFMA2(acc[0][0], a01.x, b01.x); FFMA2(acc[0][1], a01.x, b01.y);
            FFMA2(acc[0][2], a01.x, b23.x); FFMA2(acc[0][3], a01.x, b23.y);
            FFMA2(acc[1][0], a01.y, b01.x); FFMA2(acc[1][1], a01.y, b01.y);
            FFMA2(acc[1][2], a01.y, b23.x); FFMA2(acc[1][3], a01.y, b23.y);
            FFMA2(acc[2][0], a23.x, b01.x); FFMA2(acc[2][1], a23.x, b01.y);
            FFMA2(acc[2][2], a23.x, b23.x); FFMA2(acc[2][3], a23.x, b23.y);
            FFMA2(acc[3][0], a23.y, b01.x); FFMA2(acc[3][1], a23.y, b01.y);
            FFMA2(acc[3][2], a23.y, b23.x); FFMA2(acc[3][3], a23.y, b23.y);
        }
        buf ^= 1;
    }

    const int gc = col0 + ty * 4;
    float4 bv4 = make_float4(bias[gc], bias[gc + 1], bias[gc + 2], bias[gc + 3]);
#pragma unroll
    for (int ii = 0; ii < 4; ++ii) {
        float2 p0 = unpack2(acc[ii][0]);
        float2 p1 = unpack2(acc[ii][1]);
        float2 p2 = unpack2(acc[ii][2]);
        float2 p3 = unpack2(acc[ii][3]);
        int r0 = row0 + tx * 8 + 2 * ii;
        if (r0 < M)
            *(float4*)(&C[(size_t)r0 * ldc + colOff + gc]) =
                make_float4(p0.x + bv4.x, p1.x + bv4.y, p2.x + bv4.z, p3.x + bv4.w);
        if (r0 + 1 < M)
            *(float4*)(&C[(size_t)(r0 + 1) * ldc + colOff + gc]) =
                make_float4(p0.y + bv4.x, p1.y + bv4.y, p2.y + bv4.z, p3.y + bv4.w);
    }
}

// ---------------------------------------------------------------------------
// Fused prep + gather (unchanged — at L2 traffic floor).
// ---------------------------------------------------------------------------
__global__ void gather_kernel(const float* __restrict__ value,
                              const float* __restrict__ refpts)
{
    __shared__ float4 sPt4[NH * 32];
    __shared__ float  sm_aw[NPOINT];
    __shared__ float  sWsum[NH];

    const int bq = blockIdx.x;
    const int b = bq / LQ;
    const int tid = threadIdx.x;

    if (tid < NH) sWsum[tid] = 0.f;
    if (tid < NPOINT) sm_aw[tid] = g_P[bq * 384 + 256 + tid];
    __syncthreads();

    if (tid < NPOINT) {
        const int p = tid;
        const int h = p >> 4;
        const int rem = p & 15;
        const int l = rem >> 2;
        const int pt = rem & 3;

        float a = sm_aw[p];
        float mx = -1e30f;
#pragma unroll
        for (int i = 0; i < 16; ++i) mx = fmaxf(mx, sm_aw[h * 16 + i]);
        float ssum = 0.f;
#pragma unroll
        for (int i = 0; i < 16; ++i) ssum += expf(sm_aw[h * 16 + i] - mx);
        float w = expf(a - mx) / ssum;

        const int Wl = c_lvlW[l];
        const int base = c_lvlStart[l];
        const float fW = (float)Wl;
        float offx = g_P[bq * 384 + (((h * 4 + l) * 4 + pt) * 2) + 0];
        float offy = g_P[bq * 384 + (((h * 4 + l) * 4 + pt) * 2) + 1];
        float rx = refpts[(bq * NL + l) * 2 + 0];
        float ry = refpts[(bq * NL + l) * 2 + 1];
        float x = (rx + offx / fW) * fW - 0.5f;
        float y = (ry + offy / fW) * fW - 0.5f;

        const float fx = floorf(x), fy = floorf(y);
        const int x0 = (int)fx, y0 = (int)fy;
        const float wx = x - fx, wy = y - fy;
        const float bw[4] = {(1.f - wx) * (1.f - wy), wx * (1.f - wy),
                             (1.f - wx) * wy,         wx * wy};
        const int dx[4] = {0, 1, 0, 1};
        const int dy[4] = {0, 0, 1, 1};
        float wt[4]; int idx4[4];
        float tsum = 0.f;
#pragma unroll
        for (int t = 0; t < 4; ++t) {
            int xi = x0 + dx[t], yi = y0 + dy[t];
            bool valid = (xi >= 0) && (xi < Wl) && (yi >= 0) && (yi < Wl);
            wt[t] = valid ? w * bw[t] : 0.f;
            int xc = min(max(xi, 0), Wl - 1);
            int yc = min(max(yi, 0), Wl - 1);
            idx4[t] = (base + yc * Wl + xc) * 64;
            tsum += wt[t];
        }
        sPt4[h * 32 + rem * 2 + 0] =
            make_float4(wt[0], __int_as_float(idx4[0]), wt[1], __int_as_float(idx4[1]));
        sPt4[h * 32 + rem * 2 + 1] =
            make_float4(wt[2], __int_as_float(idx4[2]), wt[3], __int_as_float(idx4[3]));
        atomicAdd(&sWsum[h], tsum);
    }
    __syncthreads();

    const int s = tid >> 6;
    const int cq = tid & 63;
    const float4* vb = (const float4*)value + (size_t)b * ((size_t)LEN_V * 64) + cq;

#pragma unroll
    for (int hh = 0; hh < 2; ++hh) {
        const int h = s * 2 + hh;
        float accx = 0.f, accy = 0.f, accz = 0.f, accw = 0.f;
#pragma unroll 4
        for (int j = 0; j < 32; j += 2) {
            float4 p0 = sPt4[h * 32 + j];
            float4 p1 = sPt4[h * 32 + j + 1];
            float4 v0 = vb[__float_as_int(p0.y)];
            float4 v1 = vb[__float_as_int(p0.w)];
            float4 v2 = vb[__float_as_int(p1.y)];
            float4 v3 = vb[__float_as_int(p1.w)];
            accx += p0.x * v0.x + p0.z * v1.x + p1.x * v2.x + p1.z * v3.x;
            accy += p0.x * v0.y + p0.z * v1.y + p1.x * v2.y + p1.z * v3.y;
            accz += p0.x * v0.z + p0.z * v1.z + p1.x * v2.z + p1.z * v3.z;
            accw += p0.x * v0.w + p0.z * v1.w + p1.x * v2.w + p1.z * v3.w;
        }
        *(float4*)&g_agg[(((size_t)h * NQ) + bq) * DIM + cq * 4] =
            make_float4(accx, accy, accz, accw);
    }
    if (tid < NH) g_wsum[bq * NH + tid] = sWsum[tid];
}

// ---------------------------------------------------------------------------
// Per-head projection, FFMA2 version. Tile 64(M) x 64(N) covering heads 2hp,
// 2hp+1. A tiles for both heads in smem; thread's head = ty>>3.
// ---------------------------------------------------------------------------
__global__ void __launch_bounds__(128) headproj_kernel(
    const float* __restrict__ Wv, const float* __restrict__ bv)
{
    __shared__ __align__(16) float As[2][16][2][68];  // [buf][k][head][row]
    __shared__ __align__(16) float Bs[2][16][128];
    const int tid = threadIdx.x;
    const int tx = tid & 7;
    const int ty = tid >> 3;          // 0..15 ; head = ty>>3
    const int hp = blockIdx.y;
    const int row0 = blockIdx.x * 64;
    const int lr = tid >> 1;          // 0..63
    const int lk = (tid & 1) * 8;

    int arow = row0 + lr; if (arow >= NQ) arow = NQ - 1;
    const float* aptr0 = g_agg + (size_t)(2 * hp) * NQ * DIM + (size_t)arow * DIM + lk;
    const float* aptr1 = g_agg + (size_t)(2 * hp + 1) * NQ * DIM + (size_t)arow * DIM + lk;
    const float* wptr  = Wv + (size_t)(hp * 64 + lr) * 256 + lk;

    unsigned long long acc[4][4];
#pragma unroll
    for (int i = 0; i < 4; ++i)
#pragma unroll
        for (int j = 0; j < 4; ++j) acc[i][j] = 0ull;

    float4 va00 = *(const float4*)(aptr0);
    float4 va01 = *(const float4*)(aptr0 + 4);
    float4 va10 = *(const float4*)(aptr1);
    float4 va11 = *(const float4*)(aptr1 + 4);
    float4 vw0  = *(const float4*)(wptr);
    float4 vw1  = *(const float4*)(wptr + 4);

    int buf = 0;
    for (int kc = 0; kc < 256; kc += 16) {
        As[buf][lk + 0][0][lr] = va00.x; As[buf][lk + 1][0][lr] = va00.y;
        As[buf][lk + 2][0][lr] = va00.z; As[buf][lk + 3][0][lr] = va00.w;
        As[buf][lk + 4][0][lr] = va01.x; As[buf][lk + 5][0][lr] = va01.y;
        As[buf][lk + 6][0][lr] = va01.z; As[buf][lk + 7][0][lr] = va01.w;
        As[buf][lk + 0][1][lr] = va10.x; As[buf][lk + 1][1][lr] = va10.y;
        As[buf][lk + 2][1][lr] = va10.z; As[buf][lk + 3][1][lr] = va10.w;
        As[buf][lk + 4][1][lr] = va11.x; As[buf][lk + 5][1][lr] = va11.y;
        As[buf][lk + 6][1][lr] = va11.z; As[buf][lk + 7][1][lr] = va11.w;
        *(float2*)&Bs[buf][lk + 0][2 * lr] = make_float2(vw0.x, vw0.x);
        *(float2*)&Bs[buf][lk + 1][2 * lr] = make_float2(vw0.y, vw0.y);
        *(float2*)&Bs[buf][lk + 2][2 * lr] = make_float2(vw0.z, vw0.z);
        *(float2*)&Bs[buf][lk + 3][2 * lr] = make_float2(vw0.w, vw0.w);
        *(float2*)&Bs[buf][lk + 4][2 * lr] = make_float2(vw1.x, vw1.x);
        *(float2*)&Bs[buf][lk + 5][2 * lr] = make_float2(vw1.y, vw1.y);
        *(float2*)&Bs[buf][lk + 6][2 * lr] = make_float2(vw1.z, vw1.z);
        *(float2*)&Bs[buf][lk + 7][2 * lr] = make_float2(vw1.w, vw1.w);
        __syncthreads();
        if (kc + 16 < 256) {
            va00 = *(const float4*)(aptr0 + kc + 16);
            va01 = *(const float4*)(aptr0 + kc + 20);
            va10 = *(const float4*)(aptr1 + kc + 16);
            va11 = *(const float4*)(aptr1 + kc + 20);
            vw0  = *(const float4*)(wptr  + kc + 16);
            vw1  = *(const float4*)(wptr  + kc + 20);
        }
        const int hd = ty >> 3;
#pragma unroll
        for (int k = 0; k < 16; ++k) {
            ulonglong2 a01 = *(const ulonglong2*)&As[buf][k][hd][tx * 8];
            ulonglong2 a23 = *(const ulonglong2*)&As[buf][k][hd][tx * 8 + 4];
            ulonglong2 b01 = *(const ulonglong2*)&Bs[buf][k][ty * 8];
            ulonglong2 b23 = *(const ulonglong2*)&Bs[buf][k][ty * 8 + 4];
            FFMA2(acc[0][0], a01.x, b01.x); FFMA2(acc[0][1], a01.x, b01.y);
            FFMA2(acc[0][2], a01.x, b23.x); FFMA2(acc[0][3], a01.x, b23.y);
            FFMA2(acc[1][0], a01.y, b01.x); FFMA2(acc[1][1], a01.y, b01.y);
            FFMA2(acc[1][2], a01.y, b23.x); FFMA2(acc[1][3], a01.y, b23.y);
            FFMA2(acc[2][0], a23.x, b01.x); FFMA2(acc[2][1], a23.x, b01.y);
            FFMA2(acc[2][2], a23.x, b23.x); FFMA2(acc[2][3], a23.x, b23.y);
            FFMA2(acc[3][0], a23.y, b01.x); FFMA2(acc[3][1], a23.y, b01.y);
            FFMA2(acc[3][2], a23.y, b23.x); FFMA2(acc[3][3], a23.y, b23.y);
        }
        buf ^= 1;
    }

    const int gc = hp * 64 + ty * 4;
    const int h = gc >> 5;
    float4 bv4 = make_float4(bv[gc], bv[gc + 1], bv[gc + 2], bv[gc + 3]);
#pragma unroll
    for (int ii = 0; ii < 4; ++ii) {
        float2 p0 = unpack2(acc[ii][0]);
        float2 p1 = unpack2(acc[ii][1]);
        float2 p2 = unpack2(acc[ii][2]);
        float2 p3 = unpack2(acc[ii][3]);
        int r0 = row0 + tx * 8 + 2 * ii;
        if (r0 < NQ) {
            float ws = g_wsum[r0 * NH + h];
            *(float4*)(&g_Y[(size_t)r0 * 256 + gc]) =
                make_float4(p0.x + ws * bv4.x, p1.x + ws * bv4.y,
                            p2.x + ws * bv4.z, p3.x + ws * bv4.w);
        }
        if (r0 + 1 < NQ) {
            float ws = g_wsum[(r0 + 1) * NH + h];
            *(float4*)(&g_Y[(size_t)(r0 + 1) * 256 + gc]) =
                make_float4(p0.y + ws * bv4.x, p1.y + ws * bv4.y,
                            p2.y + ws * bv4.z, p3.y + ws * bv4.w);
        }
    }
}

// ---------------------------------------------------------------------------
extern "C" void kernel_launch(void* const* d_in, const int* in_sizes, int n_in,
                              void* d_out, int out_size) {
    const float* query  = (const float*)d_in[0];
    const float* refpts = (const float*)d_in[1];
    const float* value  = (const float*)d_in[2];
    const float* Wv     = (const float*)d_in[3];
    const float* bv     = (const float*)d_in[4];
    const float* Woff   = (const float*)d_in[5];
    const float* boff   = (const float*)d_in[6];
    const float* Wattn  = (const float*)d_in[7];
    const float* battn  = (const float*)d_in[8];
    const float* Wout   = (const float*)d_in[9];
    const float* bout   = (const float*)d_in[10];
    float* out = (float*)d_out;

    float *pP = nullptr, *pY = nullptr;
    cudaGetSymbolAddress((void**)&pP, g_P);
    cudaGetSymbolAddress((void**)&pY, g_Y);

    const int MB = (NQ + 63) / 64;   // 38

    // qproj: y 0..3 -> Woff (cols 0..255), y 4..5 -> Wattn (cols 256..383)
    gemm_dual_kernel<<<dim3(MB, 6), 128>>>(query, 256, Woff, boff, 4,
                                           Wattn, battn, pP, 384, NQ);
    // fused softmax/loc prep + weighted value gather -> g_agg [h][q][c], g_wsum
    gather_kernel<<<NQ, 256>>>(value, refpts);
    // per-head value projection on aggregates -> g_Y [2400 x 256]
    headproj_kernel<<<dim3(MB, 4), 128>>>(Wv, bv);
    // output projection -> out
    gemm_dual_kernel<<<dim3(MB, 4), 128>>>(pY, 256, Wout, bout, 4,
                                           (const float*)nullptr,
                                           (const float*)nullptr, out, 256, NQ);
}

// round 7
// speedup vs baseline: 1.0460x; 1.0460x over previous
#include <cuda_runtime.h>
#include <math.h>
#include <string.h>

#define BS 8
#define LQ 300
#define NQ (BS*LQ)        // 2400
#define DIM 256
#define NH 8
#define NL 4
#define NP 4
#define LEN_V 34000
#define NPOINT 128        // NH*NL*NP

__constant__ int c_lvlW[4]     = {160, 80, 40, 20};
__constant__ int c_lvlStart[4] = {0, 25600, 32000, 33600};

// Scratch
__device__ float g_P[NQ * 384];                    // [off(256) | attn(128)]
__device__ float g_agg[(size_t)NH * NQ * DIM];     // [h][q][c]
__device__ float g_wsum[NQ * NH];
__device__ float g_Y[NQ * DIM];

// Packed fp32x2 FMA (Blackwell): per-lane d = a*b + d on a 64-bit register pair.
#define FFMA2(c, a, b) asm("fma.rn.f32x2 %0, %1, %2, %0;" : "+l"(c) : "l"(a), "l"(b))

__device__ __forceinline__ float2 unpack2(unsigned long long v) {
    float2 f; memcpy(&f, &v, 8); return f;
}

// ---------------------------------------------------------------------------
// FFMA2 GEMM, dual weight set. Tile 32(M) x 64(N), 128 threads, grid.x = 75
// (2-3 blocks/SM — the occupancy that worked in round 5).
// Micro-tile: 4 rows (2 packed f32x2 pairs) x 4 cols; 8 FFMA2 + 3 LDS.128 per k.
// B duplicated in smem so packed b operands come straight from LDS.128.
// ---------------------------------------------------------------------------
__global__ void __launch_bounds__(128) gemm_dual_kernel(
    const float* __restrict__ A, int lda,
    const float* __restrict__ W0, const float* __restrict__ b0, int nyW0,
    const float* __restrict__ W1, const float* __restrict__ b1,
    float* __restrict__ C, int ldc, int M)
{
    __shared__ __align__(16) float As[2][16][40];    // [buf][k][row], 160B rows
    __shared__ __align__(16) float Bs[2][16][136];   // [buf][k][2j]=[2j+1]=b_j
    const int tid = threadIdx.x;
    const int tx = tid & 7;           // rows tx*4 .. tx*4+3
    const int ty = tid >> 3;          // cols ty*4 .. ty*4+3 (0..15)
    const int row0 = blockIdx.x * 32;
    const int ar = tid >> 2;          // 0..31 (A load row)
    const int akq = (tid & 3) * 4;
    const int br = tid >> 1;          // 0..63 (B load col)
    const int bkq = (tid & 1) * 8;

    const float* W; const float* bias; int col0, colOff;
    if ((int)blockIdx.y < nyW0) {
        W = W0; bias = b0; col0 = blockIdx.y * 64; colOff = 0;
    } else {
        W = W1; bias = b1; col0 = (blockIdx.y - nyW0) * 64; colOff = nyW0 * 64;
    }

    int arow = row0 + ar; if (arow >= M) arow = M - 1;
    const float* aptr = A + (size_t)arow * lda + akq;
    const float* wptr = W + (size_t)(col0 + br) * 256 + bkq;

    unsigned long long acc[2][4];
#pragma unroll
    for (int i = 0; i < 2; ++i)
#pragma unroll
        for (int j = 0; j < 4; ++j) acc[i][j] = 0ull;

    float4 va  = *(const float4*)(aptr);
    float4 vw0 = *(const float4*)(wptr);
    float4 vw1 = *(const float4*)(wptr + 4);

    int buf = 0;
    for (int kc = 0; kc < 256; kc += 16) {
        As[buf][akq + 0][ar] = va.x;  As[buf][akq + 1][ar] = va.y;
        As[buf][akq + 2][ar] = va.z;  As[buf][akq + 3][ar] = va.w;
        *(float2*)&Bs[buf][bkq + 0][2 * br] = make_float2(vw0.x, vw0.x);
        *(float2*)&Bs[buf][bkq + 1][2 * br] = make_float2(vw0.y, vw0.y);
        *(float2*)&Bs[buf][bkq + 2][2 * br] = make_float2(vw0.z, vw0.z);
        *(float2*)&Bs[buf][bkq + 3][2 * br] = make_float2(vw0.w, vw0.w);
        *(float2*)&Bs[buf][bkq + 4][2 * br] = make_float2(vw1.x, vw1.x);
        *(float2*)&Bs[buf][bkq + 5][2 * br] = make_float2(vw1.y, vw1.y);
        *(float2*)&Bs[buf][bkq + 6][2 * br] = make_float2(vw1.z, vw1.z);
        *(float2*)&Bs[buf][bkq + 7][2 * br] = make_float2(vw1.w, vw1.w);
        __syncthreads();
        if (kc + 16 < 256) {
            va  = *(const float4*)(aptr + kc + 16);
            vw0 = *(const float4*)(wptr + kc + 16);
            vw1 = *(const float4*)(wptr + kc + 20);
        }
#pragma unroll
        for (int k = 0; k < 16; ++k) {
            ulonglong2 a   = *(const ulonglong2*)&As[buf][k][tx * 4];
            ulonglong2 b01 = *(const ulonglong2*)&Bs[buf][k][ty * 8];
            ulonglong2 b23 = *(const ulonglong2*)&Bs[buf][k][ty * 8 + 4];
            FFMA2(acc[0][0], a.x, b01.x); FFMA2(acc[0][1], a.x, b01.y);
            FFMA2(acc[0][2], a.x, b23.x); FFMA2(acc[0][3], a.x, b23.y);
            FFMA2(acc[1][0], a.y, b01.x); FFMA2(acc[1][1], a.y, b01.y);
            FFMA2(acc[1][2], a.y, b23.x); FFMA2(acc[1][3], a.y, b23.y);
        }
        buf ^= 1;
    }

    const int gc = col0 + ty * 4;
    float4 bv4 = make_float4(bias[gc], bias[gc + 1], bias[gc + 2], bias[gc + 3]);
#pragma unroll
    for (int ii = 0; ii < 2; ++ii) {
        float2 p0 = unpack2(acc[ii][0]);
        float2 p1 = unpack2(acc[ii][1]);
        float2 p2 = unpack2(acc[ii][2]);
        float2 p3 = unpack2(acc[ii][3]);
        int r0 = row0 + tx * 4 + 2 * ii;
        if (r0 < M)
            *(float4*)(&C[(size_t)r0 * ldc + colOff + gc]) =
                make_float4(p0.x + bv4.x, p1.x + bv4.y, p2.x + bv4.z, p3.x + bv4.w);
        if (r0 + 1 < M)
            *(float4*)(&C[(size_t)(r0 + 1) * ldc + colOff + gc]) =
                make_float4(p0.y + bv4.x, p1.y + bv4.y, p2.y + bv4.z, p3.y + bv4.w);
    }
}

// ---------------------------------------------------------------------------
// Fused prep + gather (unchanged — proven round-5 hot path).
// ---------------------------------------------------------------------------
__global__ void gather_kernel(const float* __restrict__ value,
                              const float* __restrict__ refpts)
{
    __shared__ float4 sPt4[NH * 32];
    __shared__ float  sm_aw[NPOINT];
    __shared__ float  sWsum[NH];

    const int bq = blockIdx.x;
    const int b = bq / LQ;
    const int tid = threadIdx.x;

    if (tid < NH) sWsum[tid] = 0.f;
    if (tid < NPOINT) sm_aw[tid] = g_P[bq * 384 + 256 + tid];
    __syncthreads();

    if (tid < NPOINT) {
        const int p = tid;
        const int h = p >> 4;
        const int rem = p & 15;
        const int l = rem >> 2;
        const int pt = rem & 3;

        float a = sm_aw[p];
        float mx = -1e30f;
#pragma unroll
        for (int i = 0; i < 16; ++i) mx = fmaxf(mx, sm_aw[h * 16 + i]);
        float ssum = 0.f;
#pragma unroll
        for (int i = 0; i < 16; ++i) ssum += expf(sm_aw[h * 16 + i] - mx);
        float w = expf(a - mx) / ssum;

        const int Wl = c_lvlW[l];
        const int base = c_lvlStart[l];
        const float fW = (float)Wl;
        float offx = g_P[bq * 384 + (((h * 4 + l) * 4 + pt) * 2) + 0];
        float offy = g_P[bq * 384 + (((h * 4 + l) * 4 + pt) * 2) + 1];
        float rx = refpts[(bq * NL + l) * 2 + 0];
        float ry = refpts[(bq * NL + l) * 2 + 1];
        float x = (rx + offx / fW) * fW - 0.5f;
        float y = (ry + offy / fW) * fW - 0.5f;

        const float fx = floorf(x), fy = floorf(y);
        const int x0 = (int)fx, y0 = (int)fy;
        const float wx = x - fx, wy = y - fy;
        const float bw[4] = {(1.f - wx) * (1.f - wy), wx * (1.f - wy),
                             (1.f - wx) * wy,         wx * wy};
        const int dx[4] = {0, 1, 0, 1};
        const int dy[4] = {0, 0, 1, 1};
        float wt[4]; int idx4[4];
        float tsum = 0.f;
#pragma unroll
        for (int t = 0; t < 4; ++t) {
            int xi = x0 + dx[t], yi = y0 + dy[t];
            bool valid = (xi >= 0) && (xi < Wl) && (yi >= 0) && (yi < Wl);
            wt[t] = valid ? w * bw[t] : 0.f;
            int xc = min(max(xi, 0), Wl - 1);
            int yc = min(max(yi, 0), Wl - 1);
            idx4[t] = (base + yc * Wl + xc) * 64;
            tsum += wt[t];
        }
        sPt4[h * 32 + rem * 2 + 0] =
            make_float4(wt[0], __int_as_float(idx4[0]), wt[1], __int_as_float(idx4[1]));
        sPt4[h * 32 + rem * 2 + 1] =
            make_float4(wt[2], __int_as_float(idx4[2]), wt[3], __int_as_float(idx4[3]));
        atomicAdd(&sWsum[h], tsum);
    }
    __syncthreads();

    const int s = tid >> 6;
    const int cq = tid & 63;
    const float4* vb = (const float4*)value + (size_t)b * ((size_t)LEN_V * 64) + cq;

#pragma unroll
    for (int hh = 0; hh < 2; ++hh) {
        const int h = s * 2 + hh;
        float accx = 0.f, accy = 0.f, accz = 0.f, accw = 0.f;
#pragma unroll 4
        for (int j = 0; j < 32; j += 2) {
            float4 p0 = sPt4[h * 32 + j];
            float4 p1 = sPt4[h * 32 + j + 1];
            float4 v0 = vb[__float_as_int(p0.y)];
            float4 v1 = vb[__float_as_int(p0.w)];
            float4 v2 = vb[__float_as_int(p1.y)];
            float4 v3 = vb[__float_as_int(p1.w)];
            accx += p0.x * v0.x + p0.z * v1.x + p1.x * v2.x + p1.z * v3.x;
            accy += p0.x * v0.y + p0.z * v1.y + p1.x * v2.y + p1.z * v3.y;
            accz += p0.x * v0.z + p0.z * v1.z + p1.x * v2.z + p1.z * v3.z;
            accw += p0.x * v0.w + p0.z * v1.w + p1.x * v2.w + p1.z * v3.w;
        }
        *(float4*)&g_agg[(((size_t)h * NQ) + bq) * DIM + cq * 4] =
            make_float4(accx, accy, accz, accw);
    }
    if (tid < NH) g_wsum[bq * NH + tid] = sWsum[tid];
}

// ---------------------------------------------------------------------------
// Per-head projection, FFMA2, tile 32(M) x 64(N), 128 threads, grid (75, 4).
// Col block hp covers heads 2hp (cols 0..31) and 2hp+1 (cols 32..63).
// ---------------------------------------------------------------------------
__global__ void __launch_bounds__(128) headproj_kernel(
    const float* __restrict__ Wv, const float* __restrict__ bv)
{
    __shared__ __align__(16) float As[2][16][2][40];   // [buf][k][head][row]
    __shared__ __align__(16) float Bs[2][16][136];
    const int tid = threadIdx.x;
    const int tx = tid & 7;
    const int ty = tid >> 3;          // 0..15 ; head = ty>>3
    const int hp = blockIdx.y;
    const int row0 = blockIdx.x * 32;
    const int ar = tid >> 2;          // 0..31
    const int akq = (tid & 3) * 4;
    const int br = tid >> 1;          // 0..63
    const int bkq = (tid & 1) * 8;

    int arow = row0 + ar; if (arow >= NQ) arow = NQ - 1;
    const float* aptr0 = g_agg + (size_t)(2 * hp) * NQ * DIM + (size_t)arow * DIM + akq;
    const float* aptr1 = g_agg + (size_t)(2 * hp + 1) * NQ * DIM + (size_t)arow * DIM + akq;
    const float* wptr  = Wv + (size_t)(hp * 64 + br) * 256 + bkq;

    unsigned long long acc[2][4];
#pragma unroll
    for (int i = 0; i < 2; ++i)
#pragma unroll
        for (int j = 0; j < 4; ++j) acc[i][j] = 0ull;

    float4 va0 = *(const float4*)(aptr0);
    float4 va1 = *(const float4*)(aptr1);
    float4 vw0 = *(const float4*)(wptr);
    float4 vw1 = *(const float4*)(wptr + 4);

    int buf = 0;
    for (int kc = 0; kc < 256; kc += 16) {
        As[buf][akq + 0][0][ar] = va0.x; As[buf][akq + 1][0][ar] = va0.y;
        As[buf][akq + 2][0][ar] = va0.z; As[buf][akq + 3][0][ar] = va0.w;
        As[buf][akq + 0][1][ar] = va1.x; As[buf][akq + 1][1][ar] = va1.y;
        As[buf][akq + 2][1][ar] = va1.z; As[buf][akq + 3][1][ar] = va1.w;
        *(float2*)&Bs[buf][bkq + 0][2 * br] = make_float2(vw0.x, vw0.x);
        *(float2*)&Bs[buf][bkq + 1][2 * br] = make_float2(vw0.y, vw0.y);
        *(float2*)&Bs[buf][bkq + 2][2 * br] = make_float2(vw0.z, vw0.z);
        *(float2*)&Bs[buf][bkq + 3][2 * br] = make_float2(vw0.w, vw0.w);
        *(float2*)&Bs[buf][bkq + 4][2 * br] = make_float2(vw1.x, vw1.x);
        *(float2*)&Bs[buf][bkq + 5][2 * br] = make_float2(vw1.y, vw1.y);
        *(float2*)&Bs[buf][bkq + 6][2 * br] = make_float2(vw1.z, vw1.z);
        *(float2*)&Bs[buf][bkq + 7][2 * br] = make_float2(vw1.w, vw1.w);
        __syncthreads();
        if (kc + 16 < 256) {
            va0 = *(const float4*)(aptr0 + kc + 16);
            va1 = *(const float4*)(aptr1 + kc + 16);
            vw0 = *(const float4*)(wptr  + kc + 16);
            vw1 = *(const float4*)(wptr  + kc + 20);
        }
        const int hd = ty >> 3;
#pragma unroll
        for (int k = 0; k < 16; ++k) {
            ulonglong2 a   = *(const ulonglong2*)&As[buf][k][hd][tx * 4];
            ulonglong2 b01 = *(const ulonglong2*)&Bs[buf][k][ty * 8];
            ulonglong2 b23 = *(const ulonglong2*)&Bs[buf][k][ty * 8 + 4];
            FFMA2(acc[0][0], a.x, b01.x); FFMA2(acc[0][1], a.x, b01.y);
            FFMA2(acc[0][2], a.x, b23.x); FFMA2(acc[0][3], a.x, b23.y);
            FFMA2(acc[1][0], a.y, b01.x); FFMA2(acc[1][1], a.y, b01.y);
            FFMA2(acc[1][2], a.y, b23.x); FFMA2(acc[1][3], a.y, b23.y);
        }
        buf ^= 1;
    }

    const int gc = hp * 64 + ty * 4;
    const int h = gc >> 5;
    float4 bv4 = make_float4(bv[gc], bv[gc + 1], bv[gc + 2], bv[gc + 3]);
#pragma unroll
    for (int ii = 0; ii < 2; ++ii) {
        float2 p0 = unpack2(acc[ii][0]);
        float2 p1 = unpack2(acc[ii][1]);
        float2 p2 = unpack2(acc[ii][2]);
        float2 p3 = unpack2(acc[ii][3]);
        int r0 = row0 + tx * 4 + 2 * ii;
        if (r0 < NQ) {
            float ws = g_wsum[r0 * NH + h];
            *(float4*)(&g_Y[(size_t)r0 * 256 + gc]) =
                make_float4(p0.x + ws * bv4.x, p1.x + ws * bv4.y,
                            p2.x + ws * bv4.z, p3.x + ws * bv4.w);
        }
        if (r0 + 1 < NQ) {
            float ws = g_wsum[(r0 + 1) * NH + h];
            *(float4*)(&g_Y[(size_t)(r0 + 1) * 256 + gc]) =
                make_float4(p0.y + ws * bv4.x, p1.y + ws * bv4.y,
                            p2.y + ws * bv4.z, p3.y + ws * bv4.w);
        }
    }
}

// ---------------------------------------------------------------------------
extern "C" void kernel_launch(void* const* d_in, const int* in_sizes, int n_in,
                              void* d_out, int out_size) {
    const float* query  = (const float*)d_in[0];
    const float* refpts = (const float*)d_in[1];
    const float* value  = (const float*)d_in[2];
    const float* Wv     = (const float*)d_in[3];
    const float* bv     = (const float*)d_in[4];
    const float* Woff   = (const float*)d_in[5];
    const float* boff   = (const float*)d_in[6];
    const float* Wattn  = (const float*)d_in[7];
    const float* battn  = (const float*)d_in[8];
    const float* Wout   = (const float*)d_in[9];
    const float* bout   = (const float*)d_in[10];
    float* out = (float*)d_out;

    float *pP = nullptr, *pY = nullptr;
    cudaGetSymbolAddress((void**)&pP, g_P);
    cudaGetSymbolAddress((void**)&pY, g_Y);

    const int MB = NQ / 32;   // 75

    // qproj: y 0..3 -> Woff (cols 0..255), y 4..5 -> Wattn (cols 256..383)
    gemm_dual_kernel<<<dim3(MB, 6), 128>>>(query, 256, Woff, boff, 4,
                                           Wattn, battn, pP, 384, NQ);
    // fused softmax/loc prep + weighted value gather -> g_agg [h][q][c], g_wsum
    gather_kernel<<<NQ, 256>>>(value, refpts);
    // per-head value projection on aggregates -> g_Y [2400 x 256]
    headproj_kernel<<<dim3(MB, 4), 128>>>(Wv, bv);
    // output projection -> out
    gemm_dual_kernel<<<dim3(MB, 4), 128>>>(pY, 256, Wout, bout, 4,
                                           (const float*)nullptr,
                                           (const float*)nullptr, out, 256, NQ);
}

// round 8
// speedup vs baseline: 1.0498x; 1.0036x over previous
#include <cuda_runtime.h>
#include <math.h>

#define BS 8
#define LQ 300
#define NQ (BS*LQ)        // 2400
#define DIM 256
#define NH 8
#define NL 4
#define NP 4
#define LEN_V 34000
#define NPOINT 128        // NH*NL*NP

__constant__ int c_lvlW[4]     = {160, 80, 40, 20};
__constant__ int c_lvlStart[4] = {0, 25600, 32000, 33600};

// Scratch
__device__ float g_P[NQ * 384];                    // [off(256) | attn(128)]
__device__ float g_agg[(size_t)NH * NQ * DIM];     // [h][q][c]
__device__ float g_wsum[NQ * NH];
__device__ float g_Y[NQ * DIM];

// ---------------------------------------------------------------------------
// Scalar-FFMA GEMM, dual weight set. Tile 16(M) x 64(N), 128 threads.
// grid.x = 150 -> 4-6 blocks/SM so LDS latency/syncs overlap across warps.
// Micro-tile 2(M) x 4(N); per k: 1 LDS.64 (A) + 1 LDS.128 (B) + 8 FFMA.
// ---------------------------------------------------------------------------
__global__ void __launch_bounds__(128) gemm_dual_kernel(
    const float* __restrict__ A, int lda,
    const float* __restrict__ W0, const float* __restrict__ b0, int nyW0,
    const float* __restrict__ W1, const float* __restrict__ b1,
    float* __restrict__ C, int ldc, int M)
{
    __shared__ __align__(16) float As[2][16][18];   // [buf][k][row(16)+pad]
    __shared__ __align__(16) float Bs[2][16][68];   // [buf][k][col(64)+pad]
    const int tid = threadIdx.x;
    const int tx = tid & 7;           // rows tx*2, tx*2+1
    const int ty = tid >> 3;          // cols ty*4 .. ty*4+3  (0..15)
    const int row0 = blockIdx.x * 16;
    const int ar = tid >> 3;          // 0..15 (A load row)
    const int akq = (tid & 7) * 2;    // A k offset (float2)
    const int br = tid >> 1;          // 0..63 (B load col)
    const int bkq = (tid & 1) * 8;    // B k offset (2x float4)

    const float* W; const float* bias; int col0, colOff;
    if ((int)blockIdx.y < nyW0) {
        W = W0; bias = b0; col0 = blockIdx.y * 64; colOff = 0;
    } else {
        W = W1; bias = b1; col0 = (blockIdx.y - nyW0) * 64; colOff = nyW0 * 64;
    }

    int arow = row0 + ar; if (arow >= M) arow = M - 1;
    const float* aptr = A + (size_t)arow * lda + akq;
    const float* wptr = W + (size_t)(col0 + br) * 256 + bkq;

    float acc[2][4];
#pragma unroll
    for (int i = 0; i < 2; ++i)
#pragma unroll
        for (int j = 0; j < 4; ++j) acc[i][j] = 0.f;

    float2 va  = *(const float2*)(aptr);
    float4 vw0 = *(const float4*)(wptr);
    float4 vw1 = *(const float4*)(wptr + 4);

    int buf = 0;
    for (int kc = 0; kc < 256; kc += 16) {
        As[buf][akq + 0][ar] = va.x;
        As[buf][akq + 1][ar] = va.y;
        Bs[buf][bkq + 0][br] = vw0.x; Bs[buf][bkq + 1][br] = vw0.y;
        Bs[buf][bkq + 2][br] = vw0.z; Bs[buf][bkq + 3][br] = vw0.w;
        Bs[buf][bkq + 4][br] = vw1.x; Bs[buf][bkq + 5][br] = vw1.y;
        Bs[buf][bkq + 6][br] = vw1.z; Bs[buf][bkq + 7][br] = vw1.w;
        __syncthreads();
        if (kc + 16 < 256) {
            va  = *(const float2*)(aptr + kc + 16);
            vw0 = *(const float4*)(wptr + kc + 16);
            vw1 = *(const float4*)(wptr + kc + 20);
        }
#pragma unroll
        for (int k = 0; k < 16; ++k) {
            float2 a2 = *(const float2*)&As[buf][k][tx * 2];
            float4 b4 = *(const float4*)&Bs[buf][k][ty * 4];
            acc[0][0] += a2.x * b4.x; acc[0][1] += a2.x * b4.y;
            acc[0][2] += a2.x * b4.z; acc[0][3] += a2.x * b4.w;
            acc[1][0] += a2.y * b4.x; acc[1][1] += a2.y * b4.y;
            acc[1][2] += a2.y * b4.z; acc[1][3] += a2.y * b4.w;
        }
        buf ^= 1;
    }

    const int gc = col0 + ty * 4;
    float4 bv4 = make_float4(bias[gc], bias[gc + 1], bias[gc + 2], bias[gc + 3]);
#pragma unroll
    for (int i = 0; i < 2; ++i) {
        int r = row0 + tx * 2 + i;
        if (r < M) {
            float4 o = make_float4(acc[i][0] + bv4.x, acc[i][1] + bv4.y,
                                   acc[i][2] + bv4.z, acc[i][3] + bv4.w);
            *(float4*)(&C[(size_t)r * ldc + colOff + gc]) = o;
        }
    }
}

// ---------------------------------------------------------------------------
// Fused prep + gather (unchanged — proven round-5 hot path, at L2 floor).
// ---------------------------------------------------------------------------
__global__ void gather_kernel(const float* __restrict__ value,
                              const float* __restrict__ refpts)
{
    __shared__ float4 sPt4[NH * 32];
    __shared__ float  sm_aw[NPOINT];
    __shared__ float  sWsum[NH];

    const int bq = blockIdx.x;
    const int b = bq / LQ;
    const int tid = threadIdx.x;

    if (tid < NH) sWsum[tid] = 0.f;
    if (tid < NPOINT) sm_aw[tid] = g_P[bq * 384 + 256 + tid];
    __syncthreads();

    if (tid < NPOINT) {
        const int p = tid;
        const int h = p >> 4;
        const int rem = p & 15;
        const int l = rem >> 2;
        const int pt = rem & 3;

        float a = sm_aw[p];
        float mx = -1e30f;
#pragma unroll
        for (int i = 0; i < 16; ++i) mx = fmaxf(mx, sm_aw[h * 16 + i]);
        float ssum = 0.f;
#pragma unroll
        for (int i = 0; i < 16; ++i) ssum += expf(sm_aw[h * 16 + i] - mx);
        float w = expf(a - mx) / ssum;

        const int Wl = c_lvlW[l];
        const int base = c_lvlStart[l];
        const float fW = (float)Wl;
        float offx = g_P[bq * 384 + (((h * 4 + l) * 4 + pt) * 2) + 0];
        float offy = g_P[bq * 384 + (((h * 4 + l) * 4 + pt) * 2) + 1];
        float rx = refpts[(bq * NL + l) * 2 + 0];
        float ry = refpts[(bq * NL + l) * 2 + 1];
        float x = (rx + offx / fW) * fW - 0.5f;
        float y = (ry + offy / fW) * fW - 0.5f;

        const float fx = floorf(x), fy = floorf(y);
        const int x0 = (int)fx, y0 = (int)fy;
        const float wx = x - fx, wy = y - fy;
        const float bw[4] = {(1.f - wx) * (1.f - wy), wx * (1.f - wy),
                             (1.f - wx) * wy,         wx * wy};
        const int dx[4] = {0, 1, 0, 1};
        const int dy[4] = {0, 0, 1, 1};
        float wt[4]; int idx4[4];
        float tsum = 0.f;
#pragma unroll
        for (int t = 0; t < 4; ++t) {
            int xi = x0 + dx[t], yi = y0 + dy[t];
            bool valid = (xi >= 0) && (xi < Wl) && (yi >= 0) && (yi < Wl);
            wt[t] = valid ? w * bw[t] : 0.f;
            int xc = min(max(xi, 0), Wl - 1);
            int yc = min(max(yi, 0), Wl - 1);
            idx4[t] = (base + yc * Wl + xc) * 64;
            tsum += wt[t];
        }
        sPt4[h * 32 + rem * 2 + 0] =
            make_float4(wt[0], __int_as_float(idx4[0]), wt[1], __int_as_float(idx4[1]));
        sPt4[h * 32 + rem * 2 + 1] =
            make_float4(wt[2], __int_as_float(idx4[2]), wt[3], __int_as_float(idx4[3]));
        atomicAdd(&sWsum[h], tsum);
    }
    __syncthreads();

    const int s = tid >> 6;
    const int cq = tid & 63;
    const float4* vb = (const float4*)value + (size_t)b * ((size_t)LEN_V * 64) + cq;

#pragma unroll
    for (int hh = 0; hh < 2; ++hh) {
        const int h = s * 2 + hh;
        float accx = 0.f, accy = 0.f, accz = 0.f, accw = 0.f;
#pragma unroll 4
        for (int j = 0; j < 32; j += 2) {
            float4 p0 = sPt4[h * 32 + j];
            float4 p1 = sPt4[h * 32 + j + 1];
            float4 v0 = vb[__float_as_int(p0.y)];
            float4 v1 = vb[__float_as_int(p0.w)];
            float4 v2 = vb[__float_as_int(p1.y)];
            float4 v3 = vb[__float_as_int(p1.w)];
            accx += p0.x * v0.x + p0.z * v1.x + p1.x * v2.x + p1.z * v3.x;
            accy += p0.x * v0.y + p0.z * v1.y + p1.x * v2.y + p1.z * v3.y;
            accz += p0.x * v0.z + p0.z * v1.z + p1.x * v2.z + p1.z * v3.z;
            accw += p0.x * v0.w + p0.z * v1.w + p1.x * v2.w + p1.z * v3.w;
        }
        *(float4*)&g_agg[(((size_t)h * NQ) + bq) * DIM + cq * 4] =
            make_float4(accx, accy, accz, accw);
    }
    if (tid < NH) g_wsum[bq * NH + tid] = sWsum[tid];
}

// ---------------------------------------------------------------------------
// Per-head projection: tile 16(M) x 64(N), 128 threads, grid (150, 4).
// Col block hp covers heads 2hp (cols 0..31) and 2hp+1 (cols 32..63).
// ---------------------------------------------------------------------------
__global__ void __launch_bounds__(128) headproj_kernel(
    const float* __restrict__ Wv, const float* __restrict__ bv)
{
    __shared__ __align__(16) float As[2][16][2][18];   // [buf][k][head][row]
    __shared__ __align__(16) float Bs[2][16][68];
    const int tid = threadIdx.x;
    const int tx = tid & 7;
    const int ty = tid >> 3;          // 0..15 ; head = ty>>3
    const int hp = blockIdx.y;
    const int row0 = blockIdx.x * 16;
    const int ar = tid >> 3;          // 0..15
    const int akq = (tid & 7) * 2;
    const int br = tid >> 1;          // 0..63
    const int bkq = (tid & 1) * 8;

    int arow = row0 + ar; if (arow >= NQ) arow = NQ - 1;
    const float* aptr0 = g_agg + (size_t)(2 * hp) * NQ * DIM + (size_t)arow * DIM + akq;
    const float* aptr1 = g_agg + (size_t)(2 * hp + 1) * NQ * DIM + (size_t)arow * DIM + akq;
    const float* wptr  = Wv + (size_t)(hp * 64 + br) * 256 + bkq;

    float acc[2][4];
#pragma unroll
    for (int i = 0; i < 2; ++i)
#pragma unroll
        for (int j = 0; j < 4; ++j) acc[i][j] = 0.f;

    float2 va0 = *(const float2*)(aptr0);
    float2 va1 = *(const float2*)(aptr1);
    float4 vw0 = *(const float4*)(wptr);
    float4 vw1 = *(const float4*)(wptr + 4);

    int buf = 0;
    for (int kc = 0; kc < 256; kc += 16) {
        As[buf][akq + 0][0][ar] = va0.x;
        As[buf][akq + 1][0][ar] = va0.y;
        As[buf][akq + 0][1][ar] = va1.x;
        As[buf][akq + 1][1][ar] = va1.y;
        Bs[buf][bkq + 0][br] = vw0.x; Bs[buf][bkq + 1][br] = vw0.y;
        Bs[buf][bkq + 2][br] = vw0.z; Bs[buf][bkq + 3][br] = vw0.w;
        Bs[buf][bkq + 4][br] = vw1.x; Bs[buf][bkq + 5][br] = vw1.y;
        Bs[buf][bkq + 6][br] = vw1.z; Bs[buf][bkq + 7][br] = vw1.w;
        __syncthreads();
        if (kc + 16 < 256) {
            va0 = *(const float2*)(aptr0 + kc + 16);
            va1 = *(const float2*)(aptr1 + kc + 16);
            vw0 = *(const float4*)(wptr  + kc + 16);
            vw1 = *(const float4*)(wptr  + kc + 20);
        }
        const int hd = ty >> 3;
#pragma unroll
        for (int k = 0; k < 16; ++k) {
            float2 a2 = *(const float2*)&As[buf][k][hd][tx * 2];
            float4 b4 = *(const float4*)&Bs[buf][k][ty * 4];
            acc[0][0] += a2.x * b4.x; acc[0][1] += a2.x * b4.y;
            acc[0][2] += a2.x * b4.z; acc[0][3] += a2.x * b4.w;
            acc[1][0] += a2.y * b4.x; acc[1][1] += a2.y * b4.y;
            acc[1][2] += a2.y * b4.z; acc[1][3] += a2.y * b4.w;
        }
        buf ^= 1;
    }

    const int gc = hp * 64 + ty * 4;
    const int h = gc >> 5;
    float4 bv4 = make_float4(bv[gc], bv[gc + 1], bv[gc + 2], bv[gc + 3]);
#pragma unroll
    for (int i = 0; i < 2; ++i) {
        int r = row0 + tx * 2 + i;
        if (r < NQ) {
            float ws = g_wsum[r * NH + h];
            float4 o = make_float4(acc[i][0] + ws * bv4.x, acc[i][1] + ws * bv4.y,
                                   acc[i][2] + ws * bv4.z, acc[i][3] + ws * bv4.w);
            *(float4*)(&g_Y[(size_t)r * 256 + gc]) = o;
        }
    }
}

// ---------------------------------------------------------------------------
extern "C" void kernel_launch(void* const* d_in, const int* in_sizes, int n_in,
                              void* d_out, int out_size) {
    const float* query  = (const float*)d_in[0];
    const float* refpts = (const float*)d_in[1];
    const float* value  = (const float*)d_in[2];
    const float* Wv     = (const float*)d_in[3];
    const float* bv     = (const float*)d_in[4];
    const float* Woff   = (const float*)d_in[5];
    const float* boff   = (const float*)d_in[6];
    const float* Wattn  = (const float*)d_in[7];
    const float* battn  = (const float*)d_in[8];
    const float* Wout   = (const float*)d_in[9];
    const float* bout   = (const float*)d_in[10];
    float* out = (float*)d_out;

    float *pP = nullptr, *pY = nullptr;
    cudaGetSymbolAddress((void**)&pP, g_P);
    cudaGetSymbolAddress((void**)&pY, g_Y);

    const int MB = NQ / 16;   // 150

    // qproj: y 0..3 -> Woff (cols 0..255), y 4..5 -> Wattn (cols 256..383)
    gemm_dual_kernel<<<dim3(MB, 6), 128>>>(query, 256, Woff, boff, 4,
                                           Wattn, battn, pP, 384, NQ);
    // fused softmax/loc prep + weighted value gather -> g_agg [h][q][c], g_wsum
    gather_kernel<<<NQ, 256>>>(value, refpts);
    // per-head value projection on aggregates -> g_Y [2400 x 256]
    headproj_kernel<<<dim3(MB, 4), 128>>>(Wv, bv);
    // output projection -> out
    gemm_dual_kernel<<<dim3(MB, 4), 128>>>(pY, 256, Wout, bout, 4,
                                           (const float*)nullptr,
                                           (const float*)nullptr, out, 256, NQ);
}